// round 15
// baseline (speedup 1.0000x reference)
#include <cuda_runtime.h>
#include <math.h>

#define SB 8
#define CH 32
#define KM 32
#define OC 32
#define SS 2048
#define DF (1.0f/2047.0f)
#define NB 128

// ---- scratch (device globals: allocation-free rule) ----
__device__ __align__(16) float g_xsum[SB*SS];            // [b][s]
__device__ float g_cpart[NB*CH];                         // per-block per-channel partials
__device__ __align__(16) float g_P[(size_t)SB*SS*KM];    // [b][t][k] fwd decay scan
__device__ __align__(16) float g_Q[(size_t)SB*SS*KM];    // [b][t][k] bwd decay scan
__device__ __align__(16) float g_wsum[KM*OC];            // [k][o]
__device__ unsigned g_bar0;                              // monotonic barrier counter
__device__ unsigned g_doneb[SB];                         // per-batch scan-done flags (monotonic, +2/launch)

struct P1 { float4 sacc[32][32]; float4 sacc2[4][32]; float sws[16][32]; };
struct P2 { float xs[SS]; float lc[64*33]; float tot[2][KM]; };
struct P3 { float ws[KM*OC]; float zt[2][32*32]; float st[2][32*33];
            int smL[2][2][32]; int smR[2][2][32]; };
union __align__(16) SMem { P1 p1; P2 p2; P3 p3; };

// replicate reference float32 coords: linspace(0,1,2048)
__device__ __forceinline__ float coordf(int i) {
    return (i == SS - 1) ? 1.0f : ((float)i) * DF;
}

// Guaranteed-reissue L2 read (no CSE/hoist).
__device__ __forceinline__ unsigned ldcg_u32(const unsigned* p) {
    unsigned v;
    asm volatile("ld.global.cg.u32 %0, [%1];" : "=r"(v) : "l"(p) : "memory");
    return v;
}

__global__ __launch_bounds__(512, 1) void k_fused(
    const float* __restrict__ x, const float* __restrict__ wla,
    const float* __restrict__ wph, const float* __restrict__ c_star,
    const float* __restrict__ dt_star, const float* __restrict__ log_poles,
    const float* __restrict__ pole_w, const float* __restrict__ pole_b,
    float* __restrict__ out)
{
    __shared__ SMem sm;
    __shared__ float sh_red[32][9];
    __shared__ float sh_pol[KM], sh_aa[KM], sh_a32[KM];
    __shared__ float sh_D;
    __shared__ unsigned sh_epoch;                        // launch cohort index (from bar0)
    int bx = blockIdx.x;
    int tid = threadIdx.x;

    // ================= Phase 1: xsum + cpart (+ wsum on blocks 0..31) =================
    {
        int b = bx >> 4, sc = bx & 15;
        int cg = tid >> 5, lane = tid & 31;
        const float4* xb = (const float4*)x;
        float4 v0 = xb[(size_t)(b * CH + 2 * cg) * (SS / 4) + sc * 32 + lane];
        float4 v1 = xb[(size_t)(b * CH + 2 * cg + 1) * (SS / 4) + sc * 32 + lane];
        sm.p1.sacc[2 * cg][lane] = v0;
        sm.p1.sacc[2 * cg + 1][lane] = v1;
        float c0 = (v0.x + v0.y) + (v0.z + v0.w);
        float c1 = (v1.x + v1.y) + (v1.z + v1.w);
        #pragma unroll
        for (int d = 16; d >= 1; d >>= 1) {
            c0 += __shfl_xor_sync(0xffffffffu, c0, d);
            c1 += __shfl_xor_sync(0xffffffffu, c1, d);
        }
        if (lane == 0) {
            g_cpart[bx * 32 + 2 * cg] = c0;
            g_cpart[bx * 32 + 2 * cg + 1] = c1;
        }
        __syncthreads();
        if (tid < 128) {
            int qq = tid & 31, part = tid >> 5;
            float4 acc = make_float4(0.f, 0.f, 0.f, 0.f);
            #pragma unroll
            for (int c = 0; c < 8; c++) {
                float4 u = sm.p1.sacc[part * 8 + c][qq];
                acc.x += u.x; acc.y += u.y; acc.z += u.z; acc.w += u.w;
            }
            sm.p1.sacc2[part][qq] = acc;
        }
        __syncthreads();
        if (tid < 32) {
            float4 a0 = sm.p1.sacc2[0][tid], a1 = sm.p1.sacc2[1][tid];
            float4 a2 = sm.p1.sacc2[2][tid], a3 = sm.p1.sacc2[3][tid];
            a0.x += a1.x + a2.x + a3.x;
            a0.y += a1.y + a2.y + a3.y;
            a0.z += a1.z + a2.z + a3.z;
            a0.w += a1.w + a2.w + a3.w;
            ((float4*)g_xsum)[b * (SS / 4) + sc * 32 + tid] = a0;
        }
        if (bx < 32) {                           // wsum row k = bx
            int k = bx, cc = tid >> 5, o = tid & 31;
            float s = 0.f;
            int idx = (k * CH + cc) * OC + o;
            s += (1.f / (1.f + expf(-wla[idx]))) * cosf(wph[idx]);
            idx = (k * CH + cc + 16) * OC + o;
            s += (1.f / (1.f + expf(-wla[idx]))) * cosf(wph[idx]);
            sm.p1.sws[cc][o] = s;
            __syncthreads();
            if (tid < 32) {
                float t = 0.f;
                #pragma unroll
                for (int j = 0; j < 16; j++) t += sm.p1.sws[j][tid];
                g_wsum[k * OC + tid] = t;
            }
        }
    }
    // ---- grid barrier 0 (wrap-free monotonic; also yields this launch's epoch) ----
    __syncthreads();
    if (tid == 0) {
        __threadfence();                                  // release
        unsigned old = atomicAdd(&g_bar0, 1u);
        unsigned target = (old & ~(unsigned)(NB - 1)) + (unsigned)NB;
        sh_epoch = target >> 7;                           // launches completed incl. this one
        while ((int)(ldcg_u32(&g_bar0) - target) < 0) __nanosleep(16);
        __threadfence();                                  // acquire
    }
    __syncthreads();
    unsigned epoch = sh_epoch;

    // ============ Poles/D: every block, redundantly, from cpart in L2 ============
    if (tid < 256) {
        int c = tid & 31, r = tid >> 5;
        float s = 0.f;
        #pragma unroll
        for (int j = 0; j < 16; j++) s += __ldcg(&g_cpart[(r * 16 + j) * 32 + c]);
        sh_red[c][r] = s;
    }
    __syncthreads();
    if (tid < 32) {
        float s = 0.f;
        #pragma unroll
        for (int r = 0; r < 8; r++) s += sh_red[tid][r];
        sh_red[tid][8] = s * (1.f / (float)(SB * SS));
    }
    __syncthreads();
    if (tid < 32) {
        int k = tid;
        float off = 0.f;
        #pragma unroll 8
        for (int cc = 0; cc < CH; cc++) off += sh_red[cc][8] * pole_w[cc * KM + k];
        off = tanhf(off + pole_b[k]);
        float vv = log_poles[k] + 0.1f * off;
        float sp = fmaxf(vv, 0.f) + log1pf(expf(-fabsf(vv)));   // softplus
        float p = fminf(fmaxf(sp, 0.1f), 100.f);
        sh_pol[k] = p;
        sh_aa[k]  = expf(-p * DF);
        sh_a32[k] = expf(-p * DF * 32.f);
        if (k == 0) {
            float mx = c_star[0];
            for (int i = 1; i < SB; i++) mx = fmaxf(mx, c_star[i]);
            sh_D = mx * dt_star[0];              // CAUSAL_SAFETY = 1
        }
    }
    __syncthreads();

    // ======= Phase 2: full-length scans, 16 blocks = (b, dir) =======
    if (bx < 16) {
        int b = bx >> 1;
        bool fwd = (bx & 1) == 0;
        ((float4*)sm.p2.xs)[tid] = __ldcg((const float4*)(g_xsum + b * SS) + tid);
        __syncthreads();

        int c = tid >> 3, m = tid & 7;           // chunk of 32 t (0..63), kgroup of 4
        float a0 = sh_aa[4*m+0], a1 = sh_aa[4*m+1];
        float a2 = sh_aa[4*m+2], a3 = sh_aa[4*m+3];
        const float4* c4 = (const float4*)sm.p2.xs + c * 8;

        // pass 1: chunk-local carries (zero seed)
        float s0 = 0.f, s1 = 0.f, s2v = 0.f, s3 = 0.f;
        if (fwd) {
            #pragma unroll
            for (int i = 0; i < 8; i++) {
                float4 v = c4[i];
                s0=fmaf(a0,s0,v.x); s1=fmaf(a1,s1,v.x); s2v=fmaf(a2,s2v,v.x); s3=fmaf(a3,s3,v.x);
                s0=fmaf(a0,s0,v.y); s1=fmaf(a1,s1,v.y); s2v=fmaf(a2,s2v,v.y); s3=fmaf(a3,s3,v.y);
                s0=fmaf(a0,s0,v.z); s1=fmaf(a1,s1,v.z); s2v=fmaf(a2,s2v,v.z); s3=fmaf(a3,s3,v.z);
                s0=fmaf(a0,s0,v.w); s1=fmaf(a1,s1,v.w); s2v=fmaf(a2,s2v,v.w); s3=fmaf(a3,s3,v.w);
            }
        } else {
            #pragma unroll
            for (int i = 7; i >= 0; i--) {
                float4 v = c4[i];
                s0=fmaf(a0,s0,v.w); s1=fmaf(a1,s1,v.w); s2v=fmaf(a2,s2v,v.w); s3=fmaf(a3,s3,v.w);
                s0=fmaf(a0,s0,v.z); s1=fmaf(a1,s1,v.z); s2v=fmaf(a2,s2v,v.z); s3=fmaf(a3,s3,v.z);
                s0=fmaf(a0,s0,v.y); s1=fmaf(a1,s1,v.y); s2v=fmaf(a2,s2v,v.y); s3=fmaf(a3,s3,v.y);
                s0=fmaf(a0,s0,v.x); s1=fmaf(a1,s1,v.x); s2v=fmaf(a2,s2v,v.x); s3=fmaf(a3,s3,v.x);
            }
        }
        sm.p2.lc[c * 33 + 4*m+0] = s0; sm.p2.lc[c * 33 + 4*m+1] = s1;
        sm.p2.lc[c * 33 + 4*m+2] = s2v; sm.p2.lc[c * 33 + 4*m+3] = s3;
        __syncthreads();

        // two-half Kogge-Stone over 64 chunks (scan order); warp = (kgroup, half)
        {
            int wrp = tid >> 5, lane = tid & 31;
            int kg = wrp >> 1, h = wrp & 1;
            int pos = h * 32 + lane;
            int q = fwd ? pos : (63 - pos);
            float exc[4];
            #pragma unroll
            for (int i = 0; i < 4; i++) {
                int k = 4 * kg + i;
                float v = sm.p2.lc[q * 33 + k];
                float Ap = sh_a32[k];
                #pragma unroll
                for (int d = 1; d < 32; d <<= 1) {
                    float up = __shfl_up_sync(0xffffffffu, v, d);
                    if (lane >= d) v = fmaf(Ap, up, v);
                    Ap = Ap * Ap;
                }
                if (h == 0 && lane == 31) sm.p2.tot[0][k] = v;
                float e = __shfl_up_sync(0xffffffffu, v, 1);
                exc[i] = (lane == 0) ? 0.f : e;
            }
            __syncthreads();
            #pragma unroll
            for (int i = 0; i < 4; i++) {
                int k = 4 * kg + i;
                float seed = exc[i];
                if (h == 1) {
                    float pw = sh_a32[k], r = 1.f;
                    int rr = lane;
                    #pragma unroll
                    for (int bit = 0; bit < 5; bit++) {
                        if ((rr >> bit) & 1) r *= pw;
                        pw *= pw;
                    }
                    seed = fmaf(r, sm.p2.tot[0][k], seed);
                }
                sm.p2.lc[q * 33 + k] = seed;
            }
        }
        __syncthreads();

        // pass 2: seeded scan, coalesced STG.128 per t covering k = 4m..4m+3
        float* Zt = (fwd ? g_P : g_Q) + (size_t)b * SS * KM;
        s0 = sm.p2.lc[c * 33 + 4*m+0]; s1 = sm.p2.lc[c * 33 + 4*m+1];
        s2v = sm.p2.lc[c * 33 + 4*m+2]; s3 = sm.p2.lc[c * 33 + 4*m+3];
        int t0 = c * 32;
        if (fwd) {
            #pragma unroll
            for (int i = 0; i < 8; i++) {
                float4 v = c4[i];
                s0=fmaf(a0,s0,v.x); s1=fmaf(a1,s1,v.x); s2v=fmaf(a2,s2v,v.x); s3=fmaf(a3,s3,v.x);
                *(float4*)(Zt + (size_t)(t0 + 4*i + 0) * KM + 4*m) = make_float4(s0,s1,s2v,s3);
                s0=fmaf(a0,s0,v.y); s1=fmaf(a1,s1,v.y); s2v=fmaf(a2,s2v,v.y); s3=fmaf(a3,s3,v.y);
                *(float4*)(Zt + (size_t)(t0 + 4*i + 1) * KM + 4*m) = make_float4(s0,s1,s2v,s3);
                s0=fmaf(a0,s0,v.z); s1=fmaf(a1,s1,v.z); s2v=fmaf(a2,s2v,v.z); s3=fmaf(a3,s3,v.z);
                *(float4*)(Zt + (size_t)(t0 + 4*i + 2) * KM + 4*m) = make_float4(s0,s1,s2v,s3);
                s0=fmaf(a0,s0,v.w); s1=fmaf(a1,s1,v.w); s2v=fmaf(a2,s2v,v.w); s3=fmaf(a3,s3,v.w);
                *(float4*)(Zt + (size_t)(t0 + 4*i + 3) * KM + 4*m) = make_float4(s0,s1,s2v,s3);
            }
        } else {
            #pragma unroll
            for (int i = 7; i >= 0; i--) {
                float4 v = c4[i];
                s0=fmaf(a0,s0,v.w); s1=fmaf(a1,s1,v.w); s2v=fmaf(a2,s2v,v.w); s3=fmaf(a3,s3,v.w);
                *(float4*)(Zt + (size_t)(t0 + 4*i + 3) * KM + 4*m) = make_float4(s0,s1,s2v,s3);
                s0=fmaf(a0,s0,v.z); s1=fmaf(a1,s1,v.z); s2v=fmaf(a2,s2v,v.z); s3=fmaf(a3,s3,v.z);
                *(float4*)(Zt + (size_t)(t0 + 4*i + 2) * KM + 4*m) = make_float4(s0,s1,s2v,s3);
                s0=fmaf(a0,s0,v.y); s1=fmaf(a1,s1,v.y); s2v=fmaf(a2,s2v,v.y); s3=fmaf(a3,s3,v.y);
                *(float4*)(Zt + (size_t)(t0 + 4*i + 1) * KM + 4*m) = make_float4(s0,s1,s2v,s3);
                s0=fmaf(a0,s0,v.x); s1=fmaf(a1,s1,v.x); s2v=fmaf(a2,s2v,v.x); s3=fmaf(a3,s3,v.x);
                *(float4*)(Zt + (size_t)(t0 + 4*i + 0) * KM + 4*m) = make_float4(s0,s1,s2v,s3);
            }
        }
        // signal: batch b's (b,dir) scan complete
        __syncthreads();
        if (tid == 0) {
            __threadfence();                              // stores -> L2 before flag
            atomicAdd(&g_doneb[b], 1u);
        }
    }

    // ======= Phase 3: windows first, then wait on OWN batch's scans, then z+GEMV =======
    {
        int b = bx >> 4;
        int s2 = tid >> 8, stid = tid & 255;
        int w = stid >> 5, lane = stid & 31;
        int tb[2];
        tb[0] = ((bx & 15) * 4 + 0 * 2 + s2) * 32;
        tb[1] = ((bx & 15) * 4 + 1 * 2 + s2) * 32;
        if (tid < 256) ((float4*)sm.p3.ws)[tid] = __ldcg((const float4*)g_wsum + tid);
        float Dv = sh_D;
        float ak = sh_aa[lane];
        float ph = sh_pol[lane] * DF;
        float inv_em = 1.f / expm1f(-ph);
        float kn = (float)lane * (1.0f / 31.0f);
        float filt = expf(-4.f * kn * kn);
        const float* Pb = g_P + (size_t)b * SS * KM;
        const float* Qb = g_Q + (size_t)b * SS * KM;

        // scan-independent work FIRST: exact float32 window search (both tiles)
        if (w == 1 || w == 2) {
            int it = w - 1;
            int t = tb[it] + lane;
            float ct = coordf(t);
            int guess = (int)(Dv * 2047.0f) + 2;
            int hi = SS - 1 - t;
            int j = min(hi, max(0, guess));
            while (j > 0 && fabsf(coordf(t + j) - ct) > Dv) j--;
            while (j < hi && fabsf(coordf(t + j + 1) - ct) <= Dv) j++;
            sm.p3.smR[s2][it][lane] = j;
            hi = t;
            j = min(hi, max(0, guess));
            while (j > 0 && fabsf(coordf(t - j) - ct) > Dv) j--;
            while (j < hi && fabsf(coordf(t - j - 1) - ct) <= Dv) j++;
            sm.p3.smL[s2][it][lane] = j;
        }
        __syncthreads();

        // wait ONLY for this batch's two scan blocks (per-batch monotonic flag)
        if (tid == 0) {
            unsigned tgt = 2u * epoch;
            while ((int)(ldcg_u32(&g_doneb[b]) - tgt) < 0) __nanosleep(16);
            __threadfence();                              // acquire
        }
        __syncthreads();

        // center loads (window-independent addresses) for BOTH tiles
        float Pv[2][4], Qpv[2][4];
        #pragma unroll
        for (int it = 0; it < 2; it++)
            #pragma unroll
            for (int q = 0; q < 4; q++) {
                int t = tb[it] + w + 8 * q;
                Pv[it][q]  = __ldcg(&Pb[(size_t)t * KM + lane]);
                Qpv[it][q] = (t + 1 < SS) ? __ldcg(&Qb[(size_t)(t + 1) * KM + lane]) : 0.f;
            }
        // window-dependent loads for BOTH tiles (32 loads in flight)
        float Pmv[2][4], Qmv[2][4];
        #pragma unroll
        for (int it = 0; it < 2; it++)
            #pragma unroll
            for (int q = 0; q < 4; q++) {
                int tl = w + 8 * q;
                int t = tb[it] + tl;
                int tm = t - sm.p3.smL[s2][it][tl] - 1;
                int tp = t + sm.p3.smR[s2][it][tl] + 1;
                Pmv[it][q] = (tm >= 0) ? __ldcg(&Pb[(size_t)tm * KM + lane]) : 0.f;
                Qmv[it][q] = (tp < SS) ? __ldcg(&Qb[(size_t)tp * KM + lane]) : 0.f;
            }

        #pragma unroll
        for (int it = 0; it < 2; it++) {
            int t0 = tb[it];
            #pragma unroll
            for (int q = 0; q < 4; q++) {        // phase A: rows tl = w + 8q, lane = k
                int tl = w + 8 * q;
                int mL = sm.p3.smL[s2][it][tl], mR = sm.p3.smR[s2][it][tl];
                float cLe = expm1f(-ph * (float)(mL + 1));
                float cRe = expm1f(-ph * (float)(mR + 1));
                float norm = fmaxf(fmaf(cLe, inv_em, cRe * inv_em) - 1.f, 1e-8f);
                float L = fmaf(-(cLe + 1.f), Pmv[it][q], Pv[it][q]);
                float R = fmaf(-(cRe + 1.f), Qmv[it][q], ak * Qpv[it][q]);
                sm.p3.zt[s2][tl * 32 + lane] = (L + R) * (filt / norm);
            }
            __syncthreads();
            #pragma unroll
            for (int q = 0; q < 4; q++) {        // phase B: GEMV
                int tl = w * 4 + q;
                const float4* zr = (const float4*)(sm.p3.zt[s2] + tl * 32);
                float acc = 0.f;
                #pragma unroll
                for (int p = 0; p < 8; p++) {
                    float4 zv = zr[p];
                    acc = fmaf(zv.x, sm.p3.ws[(p * 4 + 0) * OC + lane], acc);
                    acc = fmaf(zv.y, sm.p3.ws[(p * 4 + 1) * OC + lane], acc);
                    acc = fmaf(zv.z, sm.p3.ws[(p * 4 + 2) * OC + lane], acc);
                    acc = fmaf(zv.w, sm.p3.ws[(p * 4 + 3) * OC + lane], acc);
                }
                sm.p3.st[s2][tl * 33 + lane] = acc;
            }
            __syncthreads();
            int o = stid >> 3, i0 = (stid & 7) * 4;
            float4 r;
            r.x = sm.p3.st[s2][(i0 + 0) * 33 + o];
            r.y = sm.p3.st[s2][(i0 + 1) * 33 + o];
            r.z = sm.p3.st[s2][(i0 + 2) * 33 + o];
            r.w = sm.p3.st[s2][(i0 + 3) * 33 + o];
            *(float4*)(out + ((size_t)(b * OC + o)) * SS + t0 + i0) = r;
            if (it == 0) __syncthreads();
        }
    }
}

extern "C" void kernel_launch(void* const* d_in, const int* in_sizes, int n_in,
                              void* d_out, int out_size) {
    // size-based input resolution
    int ix = -1, ic = -1, idt = -1, iwla = -1, iwph = -1, ilp = -1, ipw = -1, ipb = -1;
    for (int i = 0; i < n_in; i++) {
        int s = in_sizes[i];
        if (s == SB * CH * SS)      { if (ix  < 0) ix  = i; }
        else if (s == SB)           { if (ic  < 0) ic  = i; }
        else if (s == KM * CH * OC) { if (iwla < 0) iwla = i; else if (iwph < 0) iwph = i; }
        else if (s == CH * KM)      { if (ipw < 0) ipw = i; }
        else if (s == KM)           { if (ilp < 0) ilp = i; else if (ipb < 0) ipb = i; }
        else if (s == 1)            { if (idt < 0) idt = i; }
    }
    const float* x   = (const float*)d_in[ix];
    const float* cs  = (const float*)d_in[ic];
    const float* dt  = (const float*)d_in[idt];
    const float* wla = (const float*)d_in[iwla];
    const float* wph = (const float*)d_in[iwph];
    const float* lp  = (const float*)d_in[ilp];
    const float* pw  = (const float*)d_in[ipw];
    const float* pb  = (const float*)d_in[ipb];
    float* out = (float*)d_out;

    k_fused<<<NB, 512>>>(x, wla, wph, cs, dt, lp, pw, pb, out);
}

// round 16
// speedup vs baseline: 1.0459x; 1.0459x over previous
#include <cuda_runtime.h>
#include <math.h>

#define SB 8
#define CH 32
#define KM 32
#define OC 32
#define SS 2048
#define DF (1.0f/2047.0f)
#define NB 128

// ---- scratch (device globals: allocation-free rule) ----
__device__ __align__(16) float g_xsum[SB*SS];            // [b][s]
__device__ float g_cpart[NB*CH];                         // per-block per-channel partials
__device__ __align__(16) float g_P[(size_t)SB*SS*KM];    // [b][t][k] fwd decay scan
__device__ __align__(16) float g_Q[(size_t)SB*SS*KM];    // [b][t][k] bwd decay scan
__device__ __align__(16) float g_wsum[KM*OC];            // [k][o]
__device__ unsigned g_bar0;                              // monotonic barrier counter
__device__ unsigned g_doneb[SB];                         // per-batch scan-done flags (monotonic, +2/launch)

struct P1 { float4 sacc[32][32]; float4 sacc2[4][32]; float sws[16][32]; };
struct P2 { float xs[SS]; float lc[64*33]; float tot[2][KM]; };
struct P3 { float ws[KM*OC]; float zt[2][32*32]; float st[2][32*33];
            int smL[2][2][32]; int smR[2][2][32]; };
union __align__(16) SMem { P1 p1; P2 p2; P3 p3; };

// replicate reference float32 coords: linspace(0,1,2048)
__device__ __forceinline__ float coordf(int i) {
    return (i == SS - 1) ? 1.0f : ((float)i) * DF;
}

// Guaranteed-reissue L2 read (no CSE/hoist).
__device__ __forceinline__ unsigned ldcg_u32(const unsigned* p) {
    unsigned v;
    asm volatile("ld.global.cg.u32 %0, [%1];" : "=r"(v) : "l"(p) : "memory");
    return v;
}

__global__ __launch_bounds__(512, 1) void k_fused(
    const float* __restrict__ x, const float* __restrict__ wla,
    const float* __restrict__ wph, const float* __restrict__ c_star,
    const float* __restrict__ dt_star, const float* __restrict__ log_poles,
    const float* __restrict__ pole_w, const float* __restrict__ pole_b,
    float* __restrict__ out)
{
    __shared__ SMem sm;
    __shared__ float sh_red[32][9];
    __shared__ float sh_pol[KM], sh_aa[KM], sh_a32[KM];
    __shared__ float sh_D;
    __shared__ unsigned sh_epoch;                        // launch cohort index (from bar0)
    int bx = blockIdx.x;
    int tid = threadIdx.x;

    // ================= Phase 1: xsum + cpart (+ wsum on blocks 0..31) =================
    {
        int b = bx >> 4, sc = bx & 15;
        int cg = tid >> 5, lane = tid & 31;
        const float4* xb = (const float4*)x;
        float4 v0 = xb[(size_t)(b * CH + 2 * cg) * (SS / 4) + sc * 32 + lane];
        float4 v1 = xb[(size_t)(b * CH + 2 * cg + 1) * (SS / 4) + sc * 32 + lane];
        sm.p1.sacc[2 * cg][lane] = v0;
        sm.p1.sacc[2 * cg + 1][lane] = v1;
        float c0 = (v0.x + v0.y) + (v0.z + v0.w);
        float c1 = (v1.x + v1.y) + (v1.z + v1.w);
        #pragma unroll
        for (int d = 16; d >= 1; d >>= 1) {
            c0 += __shfl_xor_sync(0xffffffffu, c0, d);
            c1 += __shfl_xor_sync(0xffffffffu, c1, d);
        }
        if (lane == 0) {
            g_cpart[bx * 32 + 2 * cg] = c0;
            g_cpart[bx * 32 + 2 * cg + 1] = c1;
        }
        __syncthreads();
        if (tid < 128) {
            int qq = tid & 31, part = tid >> 5;
            float4 acc = make_float4(0.f, 0.f, 0.f, 0.f);
            #pragma unroll
            for (int c = 0; c < 8; c++) {
                float4 u = sm.p1.sacc[part * 8 + c][qq];
                acc.x += u.x; acc.y += u.y; acc.z += u.z; acc.w += u.w;
            }
            sm.p1.sacc2[part][qq] = acc;
        }
        __syncthreads();
        if (tid < 32) {
            float4 a0 = sm.p1.sacc2[0][tid], a1 = sm.p1.sacc2[1][tid];
            float4 a2 = sm.p1.sacc2[2][tid], a3 = sm.p1.sacc2[3][tid];
            a0.x += a1.x + a2.x + a3.x;
            a0.y += a1.y + a2.y + a3.y;
            a0.z += a1.z + a2.z + a3.z;
            a0.w += a1.w + a2.w + a3.w;
            ((float4*)g_xsum)[b * (SS / 4) + sc * 32 + tid] = a0;
        }
        if (bx < 32) {                           // wsum row k = bx
            int k = bx, cc = tid >> 5, o = tid & 31;
            float s = 0.f;
            int idx = (k * CH + cc) * OC + o;
            s += (1.f / (1.f + expf(-wla[idx]))) * cosf(wph[idx]);
            idx = (k * CH + cc + 16) * OC + o;
            s += (1.f / (1.f + expf(-wla[idx]))) * cosf(wph[idx]);
            sm.p1.sws[cc][o] = s;
            __syncthreads();
            if (tid < 32) {
                float t = 0.f;
                #pragma unroll
                for (int j = 0; j < 16; j++) t += sm.p1.sws[j][tid];
                g_wsum[k * OC + tid] = t;
            }
        }
    }
    // ---- grid barrier 0 (wrap-free monotonic; also yields this launch's epoch) ----
    __syncthreads();
    if (tid == 0) {
        __threadfence();                                  // release
        unsigned old = atomicAdd(&g_bar0, 1u);
        unsigned target = (old & ~(unsigned)(NB - 1)) + (unsigned)NB;
        sh_epoch = target >> 7;                           // launches completed incl. this one
        while ((int)(ldcg_u32(&g_bar0) - target) < 0) __nanosleep(16);
        __threadfence();                                  // acquire
    }
    __syncthreads();
    unsigned epoch = sh_epoch;

    // ============ Poles/D: every block, redundantly, from cpart in L2 ============
    if (tid < 256) {
        int c = tid & 31, r = tid >> 5;
        float s = 0.f;
        #pragma unroll
        for (int j = 0; j < 16; j++) s += __ldcg(&g_cpart[(r * 16 + j) * 32 + c]);
        sh_red[c][r] = s;
    }
    __syncthreads();
    if (tid < 32) {
        float s = 0.f;
        #pragma unroll
        for (int r = 0; r < 8; r++) s += sh_red[tid][r];
        sh_red[tid][8] = s * (1.f / (float)(SB * SS));
    }
    __syncthreads();
    if (tid < 32) {
        int k = tid;
        float off = 0.f;
        #pragma unroll 8
        for (int cc = 0; cc < CH; cc++) off += sh_red[cc][8] * pole_w[cc * KM + k];
        off = tanhf(off + pole_b[k]);
        float vv = log_poles[k] + 0.1f * off;
        float sp = fmaxf(vv, 0.f) + log1pf(expf(-fabsf(vv)));   // softplus
        float p = fminf(fmaxf(sp, 0.1f), 100.f);
        sh_pol[k] = p;
        sh_aa[k]  = expf(-p * DF);
        sh_a32[k] = expf(-p * DF * 32.f);
        if (k == 0) {
            float mx = c_star[0];
            for (int i = 1; i < SB; i++) mx = fmaxf(mx, c_star[i]);
            sh_D = mx * dt_star[0];              // CAUSAL_SAFETY = 1
        }
    }
    __syncthreads();

    // ======= Phase 2: full-length scans, 16 blocks = (b, dir) =======
    if (bx < 16) {
        int b = bx >> 1;
        bool fwd = (bx & 1) == 0;
        ((float4*)sm.p2.xs)[tid] = __ldcg((const float4*)(g_xsum + b * SS) + tid);
        __syncthreads();

        int c = tid >> 3, m = tid & 7;           // chunk of 32 t (0..63), kgroup of 4
        float a0 = sh_aa[4*m+0], a1 = sh_aa[4*m+1];
        float a2 = sh_aa[4*m+2], a3 = sh_aa[4*m+3];
        const float4* c4 = (const float4*)sm.p2.xs + c * 8;

        // pass 1: chunk-local carries (zero seed)
        float s0 = 0.f, s1 = 0.f, s2v = 0.f, s3 = 0.f;
        if (fwd) {
            #pragma unroll
            for (int i = 0; i < 8; i++) {
                float4 v = c4[i];
                s0=fmaf(a0,s0,v.x); s1=fmaf(a1,s1,v.x); s2v=fmaf(a2,s2v,v.x); s3=fmaf(a3,s3,v.x);
                s0=fmaf(a0,s0,v.y); s1=fmaf(a1,s1,v.y); s2v=fmaf(a2,s2v,v.y); s3=fmaf(a3,s3,v.y);
                s0=fmaf(a0,s0,v.z); s1=fmaf(a1,s1,v.z); s2v=fmaf(a2,s2v,v.z); s3=fmaf(a3,s3,v.z);
                s0=fmaf(a0,s0,v.w); s1=fmaf(a1,s1,v.w); s2v=fmaf(a2,s2v,v.w); s3=fmaf(a3,s3,v.w);
            }
        } else {
            #pragma unroll
            for (int i = 7; i >= 0; i--) {
                float4 v = c4[i];
                s0=fmaf(a0,s0,v.w); s1=fmaf(a1,s1,v.w); s2v=fmaf(a2,s2v,v.w); s3=fmaf(a3,s3,v.w);
                s0=fmaf(a0,s0,v.z); s1=fmaf(a1,s1,v.z); s2v=fmaf(a2,s2v,v.z); s3=fmaf(a3,s3,v.z);
                s0=fmaf(a0,s0,v.y); s1=fmaf(a1,s1,v.y); s2v=fmaf(a2,s2v,v.y); s3=fmaf(a3,s3,v.y);
                s0=fmaf(a0,s0,v.x); s1=fmaf(a1,s1,v.x); s2v=fmaf(a2,s2v,v.x); s3=fmaf(a3,s3,v.x);
            }
        }
        sm.p2.lc[c * 33 + 4*m+0] = s0; sm.p2.lc[c * 33 + 4*m+1] = s1;
        sm.p2.lc[c * 33 + 4*m+2] = s2v; sm.p2.lc[c * 33 + 4*m+3] = s3;
        __syncthreads();

        // two-half Kogge-Stone over 64 chunks (scan order); warp = (kgroup, half)
        {
            int wrp = tid >> 5, lane = tid & 31;
            int kg = wrp >> 1, h = wrp & 1;
            int pos = h * 32 + lane;
            int q = fwd ? pos : (63 - pos);
            float exc[4];
            #pragma unroll
            for (int i = 0; i < 4; i++) {
                int k = 4 * kg + i;
                float v = sm.p2.lc[q * 33 + k];
                float Ap = sh_a32[k];
                #pragma unroll
                for (int d = 1; d < 32; d <<= 1) {
                    float up = __shfl_up_sync(0xffffffffu, v, d);
                    if (lane >= d) v = fmaf(Ap, up, v);
                    Ap = Ap * Ap;
                }
                if (h == 0 && lane == 31) sm.p2.tot[0][k] = v;
                float e = __shfl_up_sync(0xffffffffu, v, 1);
                exc[i] = (lane == 0) ? 0.f : e;
            }
            __syncthreads();
            #pragma unroll
            for (int i = 0; i < 4; i++) {
                int k = 4 * kg + i;
                float seed = exc[i];
                if (h == 1) {
                    float pw = sh_a32[k], r = 1.f;
                    int rr = lane;
                    #pragma unroll
                    for (int bit = 0; bit < 5; bit++) {
                        if ((rr >> bit) & 1) r *= pw;
                        pw *= pw;
                    }
                    seed = fmaf(r, sm.p2.tot[0][k], seed);
                }
                sm.p2.lc[q * 33 + k] = seed;
            }
        }
        __syncthreads();

        // pass 2: seeded scan, coalesced STG.128 per t covering k = 4m..4m+3
        float* Zt = (fwd ? g_P : g_Q) + (size_t)b * SS * KM;
        s0 = sm.p2.lc[c * 33 + 4*m+0]; s1 = sm.p2.lc[c * 33 + 4*m+1];
        s2v = sm.p2.lc[c * 33 + 4*m+2]; s3 = sm.p2.lc[c * 33 + 4*m+3];
        int t0 = c * 32;
        if (fwd) {
            #pragma unroll
            for (int i = 0; i < 8; i++) {
                float4 v = c4[i];
                s0=fmaf(a0,s0,v.x); s1=fmaf(a1,s1,v.x); s2v=fmaf(a2,s2v,v.x); s3=fmaf(a3,s3,v.x);
                *(float4*)(Zt + (size_t)(t0 + 4*i + 0) * KM + 4*m) = make_float4(s0,s1,s2v,s3);
                s0=fmaf(a0,s0,v.y); s1=fmaf(a1,s1,v.y); s2v=fmaf(a2,s2v,v.y); s3=fmaf(a3,s3,v.y);
                *(float4*)(Zt + (size_t)(t0 + 4*i + 1) * KM + 4*m) = make_float4(s0,s1,s2v,s3);
                s0=fmaf(a0,s0,v.z); s1=fmaf(a1,s1,v.z); s2v=fmaf(a2,s2v,v.z); s3=fmaf(a3,s3,v.z);
                *(float4*)(Zt + (size_t)(t0 + 4*i + 2) * KM + 4*m) = make_float4(s0,s1,s2v,s3);
                s0=fmaf(a0,s0,v.w); s1=fmaf(a1,s1,v.w); s2v=fmaf(a2,s2v,v.w); s3=fmaf(a3,s3,v.w);
                *(float4*)(Zt + (size_t)(t0 + 4*i + 3) * KM + 4*m) = make_float4(s0,s1,s2v,s3);
            }
        } else {
            #pragma unroll
            for (int i = 7; i >= 0; i--) {
                float4 v = c4[i];
                s0=fmaf(a0,s0,v.w); s1=fmaf(a1,s1,v.w); s2v=fmaf(a2,s2v,v.w); s3=fmaf(a3,s3,v.w);
                *(float4*)(Zt + (size_t)(t0 + 4*i + 3) * KM + 4*m) = make_float4(s0,s1,s2v,s3);
                s0=fmaf(a0,s0,v.z); s1=fmaf(a1,s1,v.z); s2v=fmaf(a2,s2v,v.z); s3=fmaf(a3,s3,v.z);
                *(float4*)(Zt + (size_t)(t0 + 4*i + 2) * KM + 4*m) = make_float4(s0,s1,s2v,s3);
                s0=fmaf(a0,s0,v.y); s1=fmaf(a1,s1,v.y); s2v=fmaf(a2,s2v,v.y); s3=fmaf(a3,s3,v.y);
                *(float4*)(Zt + (size_t)(t0 + 4*i + 1) * KM + 4*m) = make_float4(s0,s1,s2v,s3);
                s0=fmaf(a0,s0,v.x); s1=fmaf(a1,s1,v.x); s2v=fmaf(a2,s2v,v.x); s3=fmaf(a3,s3,v.x);
                *(float4*)(Zt + (size_t)(t0 + 4*i + 0) * KM + 4*m) = make_float4(s0,s1,s2v,s3);
            }
        }
        // signal: batch b's (b,dir) scan complete
        __syncthreads();
        if (tid == 0) {
            __threadfence();                              // stores -> L2 before flag
            atomicAdd(&g_doneb[b], 1u);
        }
    }

    // ======= Phase 3: windows first, then wait on OWN batch's scans, then z+GEMV =======
    {
        int b = bx >> 4;
        int s2 = tid >> 8, stid = tid & 255;
        int w = stid >> 5, lane = stid & 31;
        int tb[2];
        tb[0] = ((bx & 15) * 4 + 0 * 2 + s2) * 32;
        tb[1] = ((bx & 15) * 4 + 1 * 2 + s2) * 32;
        if (tid < 256) ((float4*)sm.p3.ws)[tid] = __ldcg((const float4*)g_wsum + tid);
        float Dv = sh_D;
        float ak = sh_aa[lane];
        float ph = sh_pol[lane] * DF;
        float inv_em = 1.f / expm1f(-ph);
        float kn = (float)lane * (1.0f / 31.0f);
        float filt = expf(-4.f * kn * kn);
        const float* Pb = g_P + (size_t)b * SS * KM;
        const float* Qb = g_Q + (size_t)b * SS * KM;

        // scan-independent work FIRST: exact float32 window search (both tiles)
        if (w == 1 || w == 2) {
            int it = w - 1;
            int t = tb[it] + lane;
            float ct = coordf(t);
            int guess = (int)(Dv * 2047.0f) + 2;
            int hi = SS - 1 - t;
            int j = min(hi, max(0, guess));
            while (j > 0 && fabsf(coordf(t + j) - ct) > Dv) j--;
            while (j < hi && fabsf(coordf(t + j + 1) - ct) <= Dv) j++;
            sm.p3.smR[s2][it][lane] = j;
            hi = t;
            j = min(hi, max(0, guess));
            while (j > 0 && fabsf(coordf(t - j) - ct) > Dv) j--;
            while (j < hi && fabsf(coordf(t - j - 1) - ct) <= Dv) j++;
            sm.p3.smL[s2][it][lane] = j;
        }
        __syncthreads();

        // wait ONLY for this batch's two scan blocks (per-batch monotonic flag)
        if (tid == 0) {
            unsigned tgt = 2u * epoch;
            while ((int)(ldcg_u32(&g_doneb[b]) - tgt) < 0) __nanosleep(16);
            __threadfence();                              // acquire
        }
        __syncthreads();

        // center loads (window-independent addresses) for BOTH tiles
        float Pv[2][4], Qpv[2][4];
        #pragma unroll
        for (int it = 0; it < 2; it++)
            #pragma unroll
            for (int q = 0; q < 4; q++) {
                int t = tb[it] + w + 8 * q;
                Pv[it][q]  = __ldcg(&Pb[(size_t)t * KM + lane]);
                Qpv[it][q] = (t + 1 < SS) ? __ldcg(&Qb[(size_t)(t + 1) * KM + lane]) : 0.f;
            }
        // window-dependent loads for BOTH tiles (32 loads in flight)
        float Pmv[2][4], Qmv[2][4];
        #pragma unroll
        for (int it = 0; it < 2; it++)
            #pragma unroll
            for (int q = 0; q < 4; q++) {
                int tl = w + 8 * q;
                int t = tb[it] + tl;
                int tm = t - sm.p3.smL[s2][it][tl] - 1;
                int tp = t + sm.p3.smR[s2][it][tl] + 1;
                Pmv[it][q] = (tm >= 0) ? __ldcg(&Pb[(size_t)tm * KM + lane]) : 0.f;
                Qmv[it][q] = (tp < SS) ? __ldcg(&Qb[(size_t)tp * KM + lane]) : 0.f;
            }

        #pragma unroll
        for (int it = 0; it < 2; it++) {
            int t0 = tb[it];
            #pragma unroll
            for (int q = 0; q < 4; q++) {        // phase A: rows tl = w + 8q, lane = k
                int tl = w + 8 * q;
                int mL = sm.p3.smL[s2][it][tl], mR = sm.p3.smR[s2][it][tl];
                float cLe = expm1f(-ph * (float)(mL + 1));
                float cRe = expm1f(-ph * (float)(mR + 1));
                float norm = fmaxf(fmaf(cLe, inv_em, cRe * inv_em) - 1.f, 1e-8f);
                float L = fmaf(-(cLe + 1.f), Pmv[it][q], Pv[it][q]);
                float R = fmaf(-(cRe + 1.f), Qmv[it][q], ak * Qpv[it][q]);
                sm.p3.zt[s2][tl * 32 + lane] = (L + R) * (filt / norm);
            }
            __syncthreads();
            #pragma unroll
            for (int q = 0; q < 4; q++) {        // phase B: GEMV
                int tl = w * 4 + q;
                const float4* zr = (const float4*)(sm.p3.zt[s2] + tl * 32);
                float acc = 0.f;
                #pragma unroll
                for (int p = 0; p < 8; p++) {
                    float4 zv = zr[p];
                    acc = fmaf(zv.x, sm.p3.ws[(p * 4 + 0) * OC + lane], acc);
                    acc = fmaf(zv.y, sm.p3.ws[(p * 4 + 1) * OC + lane], acc);
                    acc = fmaf(zv.z, sm.p3.ws[(p * 4 + 2) * OC + lane], acc);
                    acc = fmaf(zv.w, sm.p3.ws[(p * 4 + 3) * OC + lane], acc);
                }
                sm.p3.st[s2][tl * 33 + lane] = acc;
            }
            __syncthreads();
            int o = stid >> 3, i0 = (stid & 7) * 4;
            float4 r;
            r.x = sm.p3.st[s2][(i0 + 0) * 33 + o];
            r.y = sm.p3.st[s2][(i0 + 1) * 33 + o];
            r.z = sm.p3.st[s2][(i0 + 2) * 33 + o];
            r.w = sm.p3.st[s2][(i0 + 3) * 33 + o];
            *(float4*)(out + ((size_t)(b * OC + o)) * SS + t0 + i0) = r;
            if (it == 0) __syncthreads();
        }
    }
}

extern "C" void kernel_launch(void* const* d_in, const int* in_sizes, int n_in,
                              void* d_out, int out_size) {
    // size-based input resolution
    int ix = -1, ic = -1, idt = -1, iwla = -1, iwph = -1, ilp = -1, ipw = -1, ipb = -1;
    for (int i = 0; i < n_in; i++) {
        int s = in_sizes[i];
        if (s == SB * CH * SS)      { if (ix  < 0) ix  = i; }
        else if (s == SB)           { if (ic  < 0) ic  = i; }
        else if (s == KM * CH * OC) { if (iwla < 0) iwla = i; else if (iwph < 0) iwph = i; }
        else if (s == CH * KM)      { if (ipw < 0) ipw = i; }
        else if (s == KM)           { if (ilp < 0) ilp = i; else if (ipb < 0) ipb = i; }
        else if (s == 1)            { if (idt < 0) idt = i; }
    }
    const float* x   = (const float*)d_in[ix];
    const float* cs  = (const float*)d_in[ic];
    const float* dt  = (const float*)d_in[idt];
    const float* wla = (const float*)d_in[iwla];
    const float* wph = (const float*)d_in[iwph];
    const float* lp  = (const float*)d_in[ilp];
    const float* pw  = (const float*)d_in[ipw];
    const float* pb  = (const float*)d_in[ipb];
    float* out = (float*)d_out;

    k_fused<<<NB, 512>>>(x, wla, wph, cs, dt, lp, pw, pb, out);
}